// round 7
// baseline (speedup 1.0000x reference)
#include <cuda_runtime.h>
#include <cuda_fp16.h>

// LightGCN 3-layer propagation, N=200000, E=3.2M, D=64+64 fused to 128.
// R7 = R6 resubmit (R6 hit a container infra failure, not a kernel error).
// Pre-scaled fp16 rows (s_L = dis * e_L) so the gather is a pure SUM — CSR
// is src-only (int), scatter does no dis gathers, epilogue recovers raw
// embeddings per-node via sqrt(deg). Gather loop is the compiler-friendly
// 4-unroll (R5's manual pipeline regressed). Streaming stores for xout/CSR
// to keep the gathered xin L2-resident.
// NOTE: __device__ globals referenced ONLY from device code.

#define USER_NUM 100000
#define N_NODES  200000
#define NE       3200000

__device__ int   g_cnt[N_NODES];
__device__ int   g_rowptr[N_NODES + 1];
__device__ float g_dis[N_NODES];        // deg>0 ? rsqrt(deg) : 0
__device__ float g_sqd[N_NODES];        // deg>0 ? sqrt(deg)  : 0
__device__ int   g_csr_src[NE];
__device__ uint2 g_s0[(size_t)N_NODES * 32];   // pre-scaled fp16 rows, 256B
__device__ uint2 g_s1[(size_t)N_NODES * 32];
__device__ uint2 g_s2[(size_t)N_NODES * 32];

// ---- fp16 <-> fp32 row-chunk helpers (4 floats <-> uint2) ------------------
__device__ __forceinline__ uint2 f4_to_h(float4 v) {
    __half2 lo = __floats2half2_rn(v.x, v.y);
    __half2 hi = __floats2half2_rn(v.z, v.w);
    uint2 u;
    u.x = *reinterpret_cast<unsigned*>(&lo);
    u.y = *reinterpret_cast<unsigned*>(&hi);
    return u;
}
__device__ __forceinline__ float4 h_to_f4(uint2 u) {
    __half2 lo = *reinterpret_cast<__half2*>(&u.x);
    __half2 hi = *reinterpret_cast<__half2*>(&u.y);
    float2 a = __half22float2(lo);
    float2 b = __half22float2(hi);
    return make_float4(a.x, a.y, b.x, b.y);
}

// ---------------------------------------------------------------------------
__global__ void k_zero() {
    int i = blockIdx.x * blockDim.x + threadIdx.x;
    int stride = gridDim.x * blockDim.x;
    for (; i < N_NODES; i += stride) g_cnt[i] = 0;
}

__global__ void k_count(const int* __restrict__ dst) {
    int i = blockIdx.x * blockDim.x + threadIdx.x;
    int stride = gridDim.x * blockDim.x;
    for (; i < NE; i += stride) {
        atomicAdd(&g_cnt[dst[i]], 1);
    }
}

// Single-block exclusive scan over g_cnt -> g_rowptr; computes dis & sqd.
// Resets g_cnt to 0 so k_scatter can reuse it as the insertion cursor.
__global__ void k_scan() {
    __shared__ int sums[1024];
    const int t = threadIdx.x;
    const int CH = (N_NODES + 1023) / 1024;   // 196
    int beg = t * CH;
    int end = beg + CH; if (end > N_NODES) end = N_NODES;

    int s = 0;
    for (int i = beg; i < end; i++) {
        int c = g_cnt[i];
        s += c;
        float fc = (float)c;
        g_dis[i] = (c > 0) ? rsqrtf(fc) : 0.0f;
        g_sqd[i] = (c > 0) ? sqrtf(fc)  : 0.0f;
    }
    sums[t] = s;
    __syncthreads();

    for (int off = 1; off < 1024; off <<= 1) {
        int v = 0;
        if (t >= off) v = sums[t - off];
        __syncthreads();
        sums[t] += v;
        __syncthreads();
    }

    int run = (t == 0) ? 0 : sums[t - 1];
    for (int i = beg; i < end; i++) {
        g_rowptr[i] = run;
        run += g_cnt[i];
        g_cnt[i] = 0;                 // becomes the scatter cursor
    }
    if (t == 1023) g_rowptr[N_NODES] = run;
}

// CSR scatter: src index only, streaming store (read-once data).
__global__ void k_scatter(const int* __restrict__ src, const int* __restrict__ dst) {
    int i = blockIdx.x * blockDim.x + threadIdx.x;
    int stride = gridDim.x * blockDim.x;
    for (; i < NE; i += stride) {
        int s = src[i];
        int d = dst[i];
        int pos = g_rowptr[d] + atomicAdd(&g_cnt[d], 1);
        __stcs(&g_csr_src[pos], s);
    }
}

// Per-lane float4 chunk of the fused 128-col row, from the original inputs.
__device__ __forceinline__ float4 load_input_chunk(
    const float4* __restrict__ ui, const float4* __restrict__ ii,
    const float4* __restrict__ ug, const float4* __restrict__ ig,
    int node, int lane)
{
    if (lane < 16) {
        return (node < USER_NUM) ? ui[node * 16 + lane]
                                 : ii[(node - USER_NUM) * 16 + lane];
    } else {
        int q = lane - 16;
        return (node < USER_NUM) ? ug[node * 16 + q]
                                 : ig[(node - USER_NUM) * 16 + q];
    }
}

// Pack inputs into pre-scaled fp16 rows: s0[n] = dis[n] * x0[n].
__global__ void k_pack(const float4* __restrict__ ui, const float4* __restrict__ ii,
                       const float4* __restrict__ ug, const float4* __restrict__ ig) {
    int idx = blockIdx.x * blockDim.x + threadIdx.x;
    int stride = gridDim.x * blockDim.x;
    const int total = N_NODES * 32;
    for (; idx < total; idx += stride) {
        int node = idx >> 5;
        int lane = idx & 31;
        float  w = __ldg(&g_dis[node]);
        float4 v = load_input_chunk(ui, ii, ug, ig, node, lane);
        v.x *= w; v.y *= w; v.z *= w; v.w *= w;
        g_s0[idx] = f4_to_h(v);
    }
}

// Pure-sum gather over pre-scaled fp16 rows (compiler-batched 4-unroll).
__device__ __forceinline__ float4 gather_node(const uint2* __restrict__ xin,
                                              int node, int lane) {
    int beg = __ldg(&g_rowptr[node]);
    int end = __ldg(&g_rowptr[node + 1]);
    float4 a = make_float4(0.f, 0.f, 0.f, 0.f);
    int i = beg;
    for (; i + 4 <= end; i += 4) {
        int s0 = __ldcs(&g_csr_src[i + 0]);
        int s1 = __ldcs(&g_csr_src[i + 1]);
        int s2 = __ldcs(&g_csr_src[i + 2]);
        int s3 = __ldcs(&g_csr_src[i + 3]);
        uint2 u0 = __ldg(&xin[s0 * 32 + lane]);
        uint2 u1 = __ldg(&xin[s1 * 32 + lane]);
        uint2 u2 = __ldg(&xin[s2 * 32 + lane]);
        uint2 u3 = __ldg(&xin[s3 * 32 + lane]);
        float4 v0 = h_to_f4(u0), v1 = h_to_f4(u1);
        float4 v2 = h_to_f4(u2), v3 = h_to_f4(u3);
        a.x += v0.x + v1.x + v2.x + v3.x;
        a.y += v0.y + v1.y + v2.y + v3.y;
        a.z += v0.z + v1.z + v2.z + v3.z;
        a.w += v0.w + v1.w + v2.w + v3.w;
    }
    for (; i < end; ++i) {
        int s = __ldcs(&g_csr_src[i]);
        float4 v = h_to_f4(__ldg(&xin[s * 32 + lane]));
        a.x += v.x; a.y += v.y; a.z += v.z; a.w += v.w;
    }
    return a;
}

// Layers 1 & 2: s_{L}[d] = dis[d]^2 * sum  (pre-scaled for the next gather).
// Buffers selected in DEVICE code. layer==1: s0 -> s1 ; layer==2: s1 -> s2
__global__ void __launch_bounds__(256) k_prop12(int layer) {
    int gtid = blockIdx.x * blockDim.x + threadIdx.x;
    int node = gtid >> 5;
    if (node >= N_NODES) return;
    int lane = threadIdx.x & 31;

    const uint2* xin  = (layer == 1) ? g_s0 : g_s1;
    uint2*       xout = (layer == 1) ? g_s1 : g_s2;

    float4 a = gather_node(xin, node, lane);
    float d  = __ldg(&g_dis[node]);
    float d2 = d * d;
    a.x *= d2; a.y *= d2; a.z *= d2; a.w *= d2;
    __stcs(&xout[node * 32 + lane], f4_to_h(a));
}

// Layer 3 fused with final reduction:
// e1 = s1*sqd, e2 = s2*sqd, e3 = dis * (sum over s2 rows)
// out = (x0 + e1 + e2 + e3) / 16, split into [int | geo] sections.
__global__ void __launch_bounds__(256) k_prop3(
    const float4* __restrict__ ui, const float4* __restrict__ ii,
    const float4* __restrict__ ug, const float4* __restrict__ ig,
    float4* __restrict__ out)
{
    int gtid = blockIdx.x * blockDim.x + threadIdx.x;
    int node = gtid >> 5;
    if (node >= N_NODES) return;
    int lane = threadIdx.x & 31;

    float4 a = gather_node(g_s2, node, lane);            // Σ s2[src]

    float dis = __ldg(&g_dis[node]);
    float sqd = __ldg(&g_sqd[node]);

    float4 base = load_input_chunk(ui, ii, ug, ig, node, lane);  // x0 (fp32)
    float4 v1 = h_to_f4(__ldg(&g_s1[node * 32 + lane]));
    float4 v2 = h_to_f4(__ldg(&g_s2[node * 32 + lane]));

    const float s = 1.0f / 16.0f;
    float4 r;
    r.x = (base.x + (v1.x + v2.x) * sqd + a.x * dis) * s;
    r.y = (base.y + (v1.y + v2.y) * sqd + a.y * dis) * s;
    r.z = (base.z + (v1.z + v2.z) * sqd + a.z * dis) * s;
    r.w = (base.w + (v1.w + v2.w) * sqd + a.w * dis) * s;

    const int geo_base = N_NODES * 16;
    if (lane < 16) out[node * 16 + lane] = r;
    else           out[geo_base + node * 16 + (lane - 16)] = r;
}

// ---------------------------------------------------------------------------
extern "C" void kernel_launch(void* const* d_in, const int* in_sizes, int n_in,
                              void* d_out, int out_size) {
    const float4* user_int = (const float4*)d_in[0];
    const float4* item_int = (const float4*)d_in[1];
    const float4* user_geo = (const float4*)d_in[2];
    const float4* item_geo = (const float4*)d_in[3];
    const int*    edge     = (const int*)d_in[4];
    const int* src = edge;        // row 0 of [2, E]
    const int* dst = edge + NE;   // row 1

    float4* out = (float4*)d_out;

    const int TB = 256;
    const int prop_blocks = (N_NODES * 32 + TB - 1) / TB;   // 25000

    k_zero<<<512, TB>>>();
    k_count<<<4096, TB>>>(dst);
    k_scan<<<1, 1024>>>();
    k_scatter<<<4096, TB>>>(src, dst);
    k_pack<<<prop_blocks, TB>>>(user_int, item_int, user_geo, item_geo);

    k_prop12<<<prop_blocks, TB>>>(1);   // layer 1: s0 -> s1
    k_prop12<<<prop_blocks, TB>>>(2);   // layer 2: s1 -> s2
    k_prop3<<<prop_blocks, TB>>>(user_int, item_int, user_geo, item_geo, out);
}

// round 8
// speedup vs baseline: 1.0247x; 1.0247x over previous
#include <cuda_runtime.h>
#include <cuda_fp16.h>

// LightGCN 3-layer propagation, N=200000, E=3.2M, D=64+64 fused to 128.
// R8 = R7 minus cache-policy hints. R7 lesson: __stcs on xout evicted the
// next layer's gather source from L2 (xout(L) == xin(L+1)) -> DRAM misses,
// +270us. All loads/stores use default caching. Kept from R7: pre-scaled
// fp16 rows (s_L = dis * e_L) making the gather a pure SUM, src-only 4B CSR,
// scatter with no per-edge dis gathers.
// NOTE: __device__ globals referenced ONLY from device code.

#define USER_NUM 100000
#define N_NODES  200000
#define NE       3200000

__device__ int   g_cnt[N_NODES];
__device__ int   g_rowptr[N_NODES + 1];
__device__ float g_dis[N_NODES];        // deg>0 ? rsqrt(deg) : 0
__device__ float g_sqd[N_NODES];        // deg>0 ? sqrt(deg)  : 0
__device__ int   g_csr_src[NE];
__device__ uint2 g_s0[(size_t)N_NODES * 32];   // pre-scaled fp16 rows, 256B
__device__ uint2 g_s1[(size_t)N_NODES * 32];
__device__ uint2 g_s2[(size_t)N_NODES * 32];

// ---- fp16 <-> fp32 row-chunk helpers (4 floats <-> uint2) ------------------
__device__ __forceinline__ uint2 f4_to_h(float4 v) {
    __half2 lo = __floats2half2_rn(v.x, v.y);
    __half2 hi = __floats2half2_rn(v.z, v.w);
    uint2 u;
    u.x = *reinterpret_cast<unsigned*>(&lo);
    u.y = *reinterpret_cast<unsigned*>(&hi);
    return u;
}
__device__ __forceinline__ float4 h_to_f4(uint2 u) {
    __half2 lo = *reinterpret_cast<__half2*>(&u.x);
    __half2 hi = *reinterpret_cast<__half2*>(&u.y);
    float2 a = __half22float2(lo);
    float2 b = __half22float2(hi);
    return make_float4(a.x, a.y, b.x, b.y);
}

// ---------------------------------------------------------------------------
__global__ void k_zero() {
    int i = blockIdx.x * blockDim.x + threadIdx.x;
    int stride = gridDim.x * blockDim.x;
    for (; i < N_NODES; i += stride) g_cnt[i] = 0;
}

__global__ void k_count(const int* __restrict__ dst) {
    int i = blockIdx.x * blockDim.x + threadIdx.x;
    int stride = gridDim.x * blockDim.x;
    for (; i < NE; i += stride) {
        atomicAdd(&g_cnt[dst[i]], 1);
    }
}

// Single-block exclusive scan over g_cnt -> g_rowptr; computes dis & sqd.
// Resets g_cnt to 0 so k_scatter can reuse it as the insertion cursor.
__global__ void k_scan() {
    __shared__ int sums[1024];
    const int t = threadIdx.x;
    const int CH = (N_NODES + 1023) / 1024;   // 196
    int beg = t * CH;
    int end = beg + CH; if (end > N_NODES) end = N_NODES;

    int s = 0;
    for (int i = beg; i < end; i++) {
        int c = g_cnt[i];
        s += c;
        float fc = (float)c;
        g_dis[i] = (c > 0) ? rsqrtf(fc) : 0.0f;
        g_sqd[i] = (c > 0) ? sqrtf(fc)  : 0.0f;
    }
    sums[t] = s;
    __syncthreads();

    for (int off = 1; off < 1024; off <<= 1) {
        int v = 0;
        if (t >= off) v = sums[t - off];
        __syncthreads();
        sums[t] += v;
        __syncthreads();
    }

    int run = (t == 0) ? 0 : sums[t - 1];
    for (int i = beg; i < end; i++) {
        g_rowptr[i] = run;
        run += g_cnt[i];
        g_cnt[i] = 0;                 // becomes the scatter cursor
    }
    if (t == 1023) g_rowptr[N_NODES] = run;
}

// CSR scatter: src index only (4B), default caching.
__global__ void k_scatter(const int* __restrict__ src, const int* __restrict__ dst) {
    int i = blockIdx.x * blockDim.x + threadIdx.x;
    int stride = gridDim.x * blockDim.x;
    for (; i < NE; i += stride) {
        int s = src[i];
        int d = dst[i];
        int pos = g_rowptr[d] + atomicAdd(&g_cnt[d], 1);
        g_csr_src[pos] = s;
    }
}

// Per-lane float4 chunk of the fused 128-col row, from the original inputs.
__device__ __forceinline__ float4 load_input_chunk(
    const float4* __restrict__ ui, const float4* __restrict__ ii,
    const float4* __restrict__ ug, const float4* __restrict__ ig,
    int node, int lane)
{
    if (lane < 16) {
        return (node < USER_NUM) ? ui[node * 16 + lane]
                                 : ii[(node - USER_NUM) * 16 + lane];
    } else {
        int q = lane - 16;
        return (node < USER_NUM) ? ug[node * 16 + q]
                                 : ig[(node - USER_NUM) * 16 + q];
    }
}

// Pack inputs into pre-scaled fp16 rows: s0[n] = dis[n] * x0[n].
__global__ void k_pack(const float4* __restrict__ ui, const float4* __restrict__ ii,
                       const float4* __restrict__ ug, const float4* __restrict__ ig) {
    int idx = blockIdx.x * blockDim.x + threadIdx.x;
    int stride = gridDim.x * blockDim.x;
    const int total = N_NODES * 32;
    for (; idx < total; idx += stride) {
        int node = idx >> 5;
        int lane = idx & 31;
        float  w = __ldg(&g_dis[node]);
        float4 v = load_input_chunk(ui, ii, ug, ig, node, lane);
        v.x *= w; v.y *= w; v.z *= w; v.w *= w;
        g_s0[idx] = f4_to_h(v);
    }
}

// Pure-sum gather over pre-scaled fp16 rows (compiler-batched 4-unroll).
__device__ __forceinline__ float4 gather_node(const uint2* __restrict__ xin,
                                              int node, int lane) {
    int beg = __ldg(&g_rowptr[node]);
    int end = __ldg(&g_rowptr[node + 1]);
    float4 a = make_float4(0.f, 0.f, 0.f, 0.f);
    int i = beg;
    for (; i + 4 <= end; i += 4) {
        int s0 = __ldg(&g_csr_src[i + 0]);
        int s1 = __ldg(&g_csr_src[i + 1]);
        int s2 = __ldg(&g_csr_src[i + 2]);
        int s3 = __ldg(&g_csr_src[i + 3]);
        uint2 u0 = __ldg(&xin[s0 * 32 + lane]);
        uint2 u1 = __ldg(&xin[s1 * 32 + lane]);
        uint2 u2 = __ldg(&xin[s2 * 32 + lane]);
        uint2 u3 = __ldg(&xin[s3 * 32 + lane]);
        float4 v0 = h_to_f4(u0), v1 = h_to_f4(u1);
        float4 v2 = h_to_f4(u2), v3 = h_to_f4(u3);
        a.x += v0.x + v1.x + v2.x + v3.x;
        a.y += v0.y + v1.y + v2.y + v3.y;
        a.z += v0.z + v1.z + v2.z + v3.z;
        a.w += v0.w + v1.w + v2.w + v3.w;
    }
    for (; i < end; ++i) {
        int s = __ldg(&g_csr_src[i]);
        float4 v = h_to_f4(__ldg(&xin[s * 32 + lane]));
        a.x += v.x; a.y += v.y; a.z += v.z; a.w += v.w;
    }
    return a;
}

// Layers 1 & 2: s_{L}[d] = dis[d]^2 * sum  (pre-scaled for the next gather).
// Buffers selected in DEVICE code. layer==1: s0 -> s1 ; layer==2: s1 -> s2
__global__ void __launch_bounds__(256) k_prop12(int layer) {
    int gtid = blockIdx.x * blockDim.x + threadIdx.x;
    int node = gtid >> 5;
    if (node >= N_NODES) return;
    int lane = threadIdx.x & 31;

    const uint2* xin  = (layer == 1) ? g_s0 : g_s1;
    uint2*       xout = (layer == 1) ? g_s1 : g_s2;

    float4 a = gather_node(xin, node, lane);
    float d  = __ldg(&g_dis[node]);
    float d2 = d * d;
    a.x *= d2; a.y *= d2; a.z *= d2; a.w *= d2;
    xout[node * 32 + lane] = f4_to_h(a);
}

// Layer 3 fused with final reduction:
// e1 = s1*sqd, e2 = s2*sqd, e3 = dis * (sum over s2 rows)
// out = (x0 + e1 + e2 + e3) / 16, split into [int | geo] sections.
__global__ void __launch_bounds__(256) k_prop3(
    const float4* __restrict__ ui, const float4* __restrict__ ii,
    const float4* __restrict__ ug, const float4* __restrict__ ig,
    float4* __restrict__ out)
{
    int gtid = blockIdx.x * blockDim.x + threadIdx.x;
    int node = gtid >> 5;
    if (node >= N_NODES) return;
    int lane = threadIdx.x & 31;

    float4 a = gather_node(g_s2, node, lane);            // Σ s2[src]

    float dis = __ldg(&g_dis[node]);
    float sqd = __ldg(&g_sqd[node]);

    float4 base = load_input_chunk(ui, ii, ug, ig, node, lane);  // x0 (fp32)
    float4 v1 = h_to_f4(__ldg(&g_s1[node * 32 + lane]));
    float4 v2 = h_to_f4(__ldg(&g_s2[node * 32 + lane]));

    const float s = 1.0f / 16.0f;
    float4 r;
    r.x = (base.x + (v1.x + v2.x) * sqd + a.x * dis) * s;
    r.y = (base.y + (v1.y + v2.y) * sqd + a.y * dis) * s;
    r.z = (base.z + (v1.z + v2.z) * sqd + a.z * dis) * s;
    r.w = (base.w + (v1.w + v2.w) * sqd + a.w * dis) * s;

    const int geo_base = N_NODES * 16;
    if (lane < 16) out[node * 16 + lane] = r;
    else           out[geo_base + node * 16 + (lane - 16)] = r;
}

// ---------------------------------------------------------------------------
extern "C" void kernel_launch(void* const* d_in, const int* in_sizes, int n_in,
                              void* d_out, int out_size) {
    const float4* user_int = (const float4*)d_in[0];
    const float4* item_int = (const float4*)d_in[1];
    const float4* user_geo = (const float4*)d_in[2];
    const float4* item_geo = (const float4*)d_in[3];
    const int*    edge     = (const int*)d_in[4];
    const int* src = edge;        // row 0 of [2, E]
    const int* dst = edge + NE;   // row 1

    float4* out = (float4*)d_out;

    const int TB = 256;
    const int prop_blocks = (N_NODES * 32 + TB - 1) / TB;   // 25000

    k_zero<<<512, TB>>>();
    k_count<<<4096, TB>>>(dst);
    k_scan<<<1, 1024>>>();
    k_scatter<<<4096, TB>>>(src, dst);
    k_pack<<<prop_blocks, TB>>>(user_int, item_int, user_geo, item_geo);

    k_prop12<<<prop_blocks, TB>>>(1);   // layer 1: s0 -> s1
    k_prop12<<<prop_blocks, TB>>>(2);   // layer 2: s1 -> s2
    k_prop3<<<prop_blocks, TB>>>(user_int, item_int, user_geo, item_geo, out);
}